// round 4
// baseline (speedup 1.0000x reference)
#include <cuda_runtime.h>
#include <cuda_bf16.h>

// Problem constants
#define BATCH 8
#define SEQ   2048
#define CDIM  768
#define KDIM  768

// Scratch (device globals: allocation-free rule)
__device__ float g_q[(size_t)BATCH * SEQ * KDIM];   // 50 MB
__device__ float g_k[(size_t)BATCH * SEQ * KDIM];   // 50 MB
__device__ float g_s[(size_t)BATCH * SEQ * SEQ];    // 134 MB

#define TILE 128
#define KT   16

// Generic batched SGEMM: C[m,n] = sum_k A[m,k] * B(k,n)
//   A is row-major [M,K] (K contiguous).
//   BT=true : B is [N,K] row-major (K contiguous)  -> C = A * B^T   (NT)
//   BT=false: B is [K,N] row-major (N contiguous)  -> C = A * B     (NN)
// M,N divisible by 128; K divisible by 16. No bounds checks.
// Double-buffered smem pipeline: prefetch tile k+1 into registers while
// computing tile k, then stage into the other smem buffer. One barrier/iter.
template <bool BT>
__global__ void __launch_bounds__(256) gemm_kernel(
    const float* __restrict__ A, const float* __restrict__ B, float* __restrict__ C,
    int M, int N, int K,
    long long sA, long long sB, long long sC)
{
    __shared__ __align__(16) float As[2][KT][TILE + 4];
    __shared__ __align__(16) float Bs[2][KT][TILE + 4];

    const int m0 = blockIdx.y * TILE;
    const int n0 = blockIdx.x * TILE;
    const float* Ab = A + (long long)blockIdx.z * sA;
    const float* Bb = B + (long long)blockIdx.z * sB;
    float* Cb = C + (long long)blockIdx.z * sC;

    const int tid = threadIdx.x;
    const int tx = tid & 15;       // 0..15 -> 8 output cols each
    const int ty = tid >> 4;       // 0..15 -> 8 output rows each

    // Per-thread load coordinates (constant across iterations)
    // A: idx = tid + r*256 -> m = idx>>2, k4 = (idx&3)*4
    // B(NT): same shape as A.  B(NN): kk = idx>>5, n4 = (idx&31)*4
    float acc[8][8];
#pragma unroll
    for (int i = 0; i < 8; i++)
#pragma unroll
        for (int j = 0; j < 8; j++) acc[i][j] = 0.0f;

    float4 pa[2], pb[2];           // prefetch staging registers

    // ---- helper lambdas ----
    auto load_regs = [&](int k0) {
#pragma unroll
        for (int r = 0; r < 2; r++) {
            int idx = tid + r * 256;
            int m  = idx >> 2;
            int k4 = (idx & 3) * 4;
            pa[r] = *(const float4*)&Ab[(long long)(m0 + m) * K + k0 + k4];
        }
        if (BT) {
#pragma unroll
            for (int r = 0; r < 2; r++) {
                int idx = tid + r * 256;
                int n  = idx >> 2;
                int k4 = (idx & 3) * 4;
                pb[r] = *(const float4*)&Bb[(long long)(n0 + n) * K + k0 + k4];
            }
        } else {
#pragma unroll
            for (int r = 0; r < 2; r++) {
                int idx = tid + r * 256;
                int kk = idx >> 5;
                int n4 = (idx & 31) * 4;
                pb[r] = *(const float4*)&Bb[(long long)(k0 + kk) * N + n0 + n4];
            }
        }
    };

    auto store_smem = [&](int buf) {
#pragma unroll
        for (int r = 0; r < 2; r++) {
            int idx = tid + r * 256;
            int m  = idx >> 2;
            int k4 = (idx & 3) * 4;
            As[buf][k4 + 0][m] = pa[r].x; As[buf][k4 + 1][m] = pa[r].y;
            As[buf][k4 + 2][m] = pa[r].z; As[buf][k4 + 3][m] = pa[r].w;
        }
        if (BT) {
#pragma unroll
            for (int r = 0; r < 2; r++) {
                int idx = tid + r * 256;
                int n  = idx >> 2;
                int k4 = (idx & 3) * 4;
                Bs[buf][k4 + 0][n] = pb[r].x; Bs[buf][k4 + 1][n] = pb[r].y;
                Bs[buf][k4 + 2][n] = pb[r].z; Bs[buf][k4 + 3][n] = pb[r].w;
            }
        } else {
#pragma unroll
            for (int r = 0; r < 2; r++) {
                int idx = tid + r * 256;
                int kk = idx >> 5;
                int n4 = (idx & 31) * 4;
                *(float4*)&Bs[buf][kk][n4] = pb[r];
            }
        }
    };

    // ---- prologue: fill buffer 0 ----
    load_regs(0);
    store_smem(0);
    __syncthreads();

    int buf = 0;
    for (int k0 = 0; k0 < K; k0 += KT) {
        const bool has_next = (k0 + KT) < K;
        if (has_next) load_regs(k0 + KT);      // global -> regs (overlaps compute)

        // ---- 8x8 microtile FMA on current buffer ----
#pragma unroll
        for (int kk = 0; kk < KT; kk++) {
            float a[8], b[8];
            *(float4*)&a[0] = *(const float4*)&As[buf][kk][ty * 8];
            *(float4*)&a[4] = *(const float4*)&As[buf][kk][ty * 8 + 4];
            *(float4*)&b[0] = *(const float4*)&Bs[buf][kk][tx * 8];
            *(float4*)&b[4] = *(const float4*)&Bs[buf][kk][tx * 8 + 4];
#pragma unroll
            for (int i = 0; i < 8; i++)
#pragma unroll
                for (int j = 0; j < 8; j++)
                    acc[i][j] += a[i] * b[j];
        }

        if (has_next) store_smem(buf ^ 1);     // regs -> other smem buffer
        __syncthreads();
        buf ^= 1;
    }

    // ---- store ----
#pragma unroll
    for (int i = 0; i < 8; i++) {
        long long row = (long long)(m0 + ty * 8 + i) * N + n0 + tx * 8;
        *(float4*)&Cb[row]     = make_float4(acc[i][0], acc[i][1], acc[i][2], acc[i][3]);
        *(float4*)&Cb[row + 4] = make_float4(acc[i][4], acc[i][5], acc[i][6], acc[i][7]);
    }
}

// Row softmax over SEQ=2048 elements, with pre-scale. One block per row.
__global__ void __launch_bounds__(256) softmax_kernel(float* __restrict__ S, float scale)
{
    float* row = S + (long long)blockIdx.x * SEQ;
    const int tid = threadIdx.x;

    float vals[8];
    float mx = -1e30f;
#pragma unroll
    for (int i = 0; i < 8; i++) {
        vals[i] = row[tid + i * 256] * scale;
        mx = fmaxf(mx, vals[i]);
    }

    __shared__ float red[256];
    red[tid] = mx;
    __syncthreads();
    for (int s = 128; s > 0; s >>= 1) {
        if (tid < s) red[tid] = fmaxf(red[tid], red[tid + s]);
        __syncthreads();
    }
    mx = red[0];
    __syncthreads();

    float sum = 0.0f;
#pragma unroll
    for (int i = 0; i < 8; i++) {
        vals[i] = __expf(vals[i] - mx);
        sum += vals[i];
    }
    red[tid] = sum;
    __syncthreads();
    for (int s = 128; s > 0; s >>= 1) {
        if (tid < s) red[tid] += red[tid + s];
        __syncthreads();
    }
    const float inv = 1.0f / red[0];
#pragma unroll
    for (int i = 0; i < 8; i++)
        row[tid + i * 256] = vals[i] * inv;
}

extern "C" void kernel_launch(void* const* d_in, const int* in_sizes, int n_in,
                              void* d_out, int out_size)
{
    const float* q_x = (const float*)d_in[0];   // [8,2048,768]
    const float* k_x = (const float*)d_in[1];   // [8,2048,768]
    const float* v_x = (const float*)d_in[2];   // [8,2048,768]
    const float* Wq  = (const float*)d_in[3];   // [768,768]
    const float* Wk  = (const float*)d_in[4];   // [768,768]
    float* out = (float*)d_out;                 // [8,2048,768]

    float *gq, *gk, *gs;
    cudaGetSymbolAddress((void**)&gq, g_q);
    cudaGetSymbolAddress((void**)&gk, g_k);
    cudaGetSymbolAddress((void**)&gs, g_s);

    const int MQ = BATCH * SEQ;   // 16384

    // Q = q_x @ Wq^T   (NT): [16384,768] x [768,768]^T
    gemm_kernel<true><<<dim3(KDIM / TILE, MQ / TILE, 1), 256>>>(
        q_x, Wq, gq, MQ, KDIM, CDIM, 0, 0, 0);
    // K = k_x @ Wk^T
    gemm_kernel<true><<<dim3(KDIM / TILE, MQ / TILE, 1), 256>>>(
        k_x, Wk, gk, MQ, KDIM, CDIM, 0, 0, 0);

    // S = Q @ K^T per batch (NT): [2048,768] x [2048,768]^T
    gemm_kernel<true><<<dim3(SEQ / TILE, SEQ / TILE, BATCH), 256>>>(
        gq, gk, gs, SEQ, SEQ, KDIM,
        (long long)SEQ * KDIM, (long long)SEQ * KDIM, (long long)SEQ * SEQ);

    // softmax(S * 1/768) row-wise
    softmax_kernel<<<BATCH * SEQ, 256>>>(gs, 1.0f / (float)KDIM);

    // out = P @ V per batch (NN): [2048,2048] x [2048,768]
    gemm_kernel<false><<<dim3(CDIM / TILE, SEQ / TILE, BATCH), 256>>>(
        gs, v_x, out, SEQ, CDIM, SEQ,
        (long long)SEQ * SEQ, (long long)SEQ * CDIM, (long long)SEQ * CDIM);
}

// round 6
// speedup vs baseline: 2.4944x; 2.4944x over previous
#include <cuda_runtime.h>
#include <cuda_bf16.h>
#include <cstdint>

#define BATCH 8
#define SEQ   2048
#define CDIM  768
#define KD    768
#define MQ    (BATCH*SEQ)

typedef __nv_bfloat16 bf16;

// ---------------- scratch (device globals; allocation-free rule) -------------
__device__ bf16  g_qx_hi[(size_t)MQ*CDIM];
__device__ bf16  g_qx_lo[(size_t)MQ*CDIM];
__device__ bf16  g_kx_hi[(size_t)MQ*CDIM];
__device__ bf16  g_kx_lo[(size_t)MQ*CDIM];
__device__ bf16  g_w_hi [(size_t)2*KD*CDIM];
__device__ bf16  g_w_lo [(size_t)2*KD*CDIM];
__device__ bf16  g_q_hi [(size_t)MQ*KD];
__device__ bf16  g_q_lo [(size_t)MQ*KD];
__device__ bf16  g_k_hi [(size_t)MQ*KD];
__device__ bf16  g_k_lo [(size_t)MQ*KD];
__device__ bf16  g_vt_hi[(size_t)BATCH*CDIM*SEQ];
__device__ bf16  g_vt_lo[(size_t)BATCH*CDIM*SEQ];
__device__ float g_s    [(size_t)BATCH*SEQ*SEQ];
__device__ bf16  g_p_hi [(size_t)BATCH*SEQ*SEQ];
__device__ bf16  g_p_lo [(size_t)BATCH*SEQ*SEQ];

// ---------------- helpers ----------------------------------------------------
__device__ __forceinline__ uint32_t smem_u32(const void* p) {
    uint32_t a;
    asm("{ .reg .u64 t; cvta.to.shared.u64 t, %1; cvt.u32.u64 %0, t; }" : "=r"(a) : "l"(p));
    return a;
}
__device__ __forceinline__ void cp16(uint32_t dst, const void* src) {
    asm volatile("cp.async.cg.shared.global [%0], [%1], 16;" :: "r"(dst), "l"(src));
}
__device__ __forceinline__ void cp_commit() {
    asm volatile("cp.async.commit_group;" ::: "memory");
}
template <int N>
__device__ __forceinline__ void cp_wait() {
    asm volatile("cp.async.wait_group %0;" :: "n"(N) : "memory");
}
__device__ __forceinline__ void ldsm4(uint32_t* r, uint32_t addr) {
    asm volatile("ldmatrix.sync.aligned.m8n8.x4.shared.b16 {%0,%1,%2,%3}, [%4];"
                 : "=r"(r[0]), "=r"(r[1]), "=r"(r[2]), "=r"(r[3]) : "r"(addr));
}
__device__ __forceinline__ void mma16816(float* c, const uint32_t* a, const uint32_t* b) {
    asm volatile(
        "mma.sync.aligned.m16n8k16.row.col.f32.bf16.bf16.f32 "
        "{%0,%1,%2,%3}, {%4,%5,%6,%7}, {%8,%9}, {%0,%1,%2,%3};"
        : "+f"(c[0]), "+f"(c[1]), "+f"(c[2]), "+f"(c[3])
        : "r"(a[0]), "r"(a[1]), "r"(a[2]), "r"(a[3]), "r"(b[0]), "r"(b[1]));
}
// fp32 -> bf16 hi/lo pair (packed as bfloat162 words)
__device__ __forceinline__ void split2(float f0, float f1, uint32_t& ph, uint32_t& pl) {
    __nv_bfloat162 hh = __floats2bfloat162_rn(f0, f1);
    float r0 = f0 - __low2float(hh);
    float r1 = f1 - __high2float(hh);
    __nv_bfloat162 ll = __floats2bfloat162_rn(r0, r1);
    ph = reinterpret_cast<uint32_t&>(hh);
    pl = reinterpret_cast<uint32_t&>(ll);
}

// ---------------- split-bf16 NT GEMM via mma.sync ----------------------------
// C[m,n] = sum_k A[m,k]*B[n,k]; A,B bf16 hi/lo, K-major. fp32 accum.
// Block 128x128, K-chunk 32, 4-stage cp.async pipeline, 8 warps (64x32 each).
#define BM 128
#define BN 128
#define BK 32
#define STAGES 4
#define PITCH_B 80               // bytes per smem row (32 bf16 + 8 pad)
#define MAT_B  (128*PITCH_B)     // 10240 bytes per matrix tile
#define STAGE_B (4*MAT_B)        // Ah, Al, Bh, Bl
#define GSMEM_BYTES (STAGES*STAGE_B)

template <bool OUT_PAIR>
__global__ void __launch_bounds__(256, 1) gemm_mma(
    const bf16* __restrict__ Ahi, const bf16* __restrict__ Alo,
    const bf16* __restrict__ Bhi, const bf16* __restrict__ Blo,
    float* __restrict__ Cf, bf16* __restrict__ Chi, bf16* __restrict__ Clo,
    int K, int N, long long sA, long long sB, long long sC)
{
    extern __shared__ char smem[];
    const uint32_t smem0 = smem_u32(smem);

    const int tid = threadIdx.x;
    const int wid = tid >> 5;
    const int lane = tid & 31;
    const int m0 = blockIdx.y * BM;
    const int n0 = blockIdx.x * BN;
    const int warp_m = (wid & 1) * 64;
    const int warp_n = (wid >> 1) * 32;

    const bf16* pAh = Ahi + (size_t)blockIdx.z * sA;
    const bf16* pAl = Alo + (size_t)blockIdx.z * sA;
    const bf16* pBh = Bhi + (size_t)blockIdx.z * sB;
    const bf16* pBl = Blo + (size_t)blockIdx.z * sB;

    float acc[4][4][4];
#pragma unroll
    for (int a = 0; a < 4; a++)
#pragma unroll
        for (int b = 0; b < 4; b++)
#pragma unroll
            for (int c = 0; c < 4; c++) acc[a][b][c] = 0.0f;

    const int nch = K / BK;

    // -------- stage loader: 128 rows x 64B per matrix, 4 matrices -----------
    auto load_stage = [&](int buf, int k0) {
        const uint32_t sb = smem0 + (uint32_t)buf * STAGE_B;
#pragma unroll
        for (int p = 0; p < 2; p++) {
            const int task = tid + p * 256;
            const int row = task >> 2;
            const int seg = task & 3;
            const uint32_t off = (uint32_t)(row * PITCH_B + seg * 16);
            const int ge = k0 + seg * 8;
            cp16(sb +             off, pAh + (size_t)(m0 + row) * K + ge);
            cp16(sb +   MAT_B   + off, pAl + (size_t)(m0 + row) * K + ge);
            cp16(sb + 2*MAT_B   + off, pBh + (size_t)(n0 + row) * K + ge);
            cp16(sb + 3*MAT_B   + off, pBl + (size_t)(n0 + row) * K + ge);
        }
    };

    // -------- prologue ------------------------------------------------------
#pragma unroll
    for (int s = 0; s < STAGES - 1; s++) {
        if (s < nch) load_stage(s, s * BK);
        cp_commit();
    }

    // precomputed fragment address offsets (within a matrix tile)
    const uint32_t a_off = (uint32_t)((lane & 15) * PITCH_B + ((lane >> 4) << 3) * 2);
    const uint32_t b_off = (uint32_t)(((((lane >> 4) << 3) + (lane & 7)) * PITCH_B)
                                      + (((lane >> 3) & 1) << 3) * 2);

    for (int ch = 0; ch < nch; ch++) {
        cp_wait<STAGES - 2>();
        __syncthreads();

        const int nxt = ch + STAGES - 1;
        if (nxt < nch) load_stage(nxt % STAGES, nxt * BK);
        cp_commit();

        const uint32_t sb = smem0 + (uint32_t)(ch % STAGES) * STAGE_B;
        const uint32_t sAh = sb, sAl = sb + MAT_B, sBh = sb + 2*MAT_B, sBl = sb + 3*MAT_B;

#pragma unroll
        for (int ks = 0; ks < 2; ks++) {
            const uint32_t kb = (uint32_t)(ks * 16 * 2);
            uint32_t ah[4][4], al[4][4];
#pragma unroll
            for (int mi = 0; mi < 4; mi++) {
                const uint32_t ad = (uint32_t)((warp_m + mi * 16) * PITCH_B) + a_off + kb;
                ldsm4(ah[mi], sAh + ad);
                ldsm4(al[mi], sAl + ad);
            }
            uint32_t bh[2][4], bl[2][4];
#pragma unroll
            for (int nj = 0; nj < 2; nj++) {
                const uint32_t bd = (uint32_t)((warp_n + nj * 16) * PITCH_B) + b_off + kb;
                ldsm4(bh[nj], sBh + bd);
                ldsm4(bl[nj], sBl + bd);
            }
#pragma unroll
            for (int mi = 0; mi < 4; mi++)
#pragma unroll
                for (int ni = 0; ni < 4; ni++) {
                    float* c = acc[mi][ni];
                    const uint32_t* Bh = &bh[ni >> 1][(ni & 1) * 2];
                    const uint32_t* Bl = &bl[ni >> 1][(ni & 1) * 2];
                    mma16816(c, ah[mi], Bh);   // hi*hi
                    mma16816(c, al[mi], Bh);   // lo*hi
                    mma16816(c, ah[mi], Bl);   // hi*lo
                }
        }
    }
    cp_wait<0>();

    // -------- epilogue ------------------------------------------------------
#pragma unroll
    for (int mi = 0; mi < 4; mi++) {
#pragma unroll
        for (int ni = 0; ni < 4; ni++) {
            const int m = m0 + warp_m + mi * 16 + (lane >> 2);
            const int n = n0 + warp_n + ni * 8 + (lane & 3) * 2;
            if (OUT_PAIR) {
                uint32_t h0, l0, h1, l1;
                split2(acc[mi][ni][0], acc[mi][ni][1], h0, l0);
                split2(acc[mi][ni][2], acc[mi][ni][3], h1, l1);
                *(uint32_t*)(Chi + (size_t)m * N + n)       = h0;
                *(uint32_t*)(Clo + (size_t)m * N + n)       = l0;
                *(uint32_t*)(Chi + (size_t)(m + 8) * N + n) = h1;
                *(uint32_t*)(Clo + (size_t)(m + 8) * N + n) = l1;
            } else {
                float* Cb = Cf + (size_t)blockIdx.z * sC;
                *(float2*)(Cb + (size_t)m * N + n)       = make_float2(acc[mi][ni][0], acc[mi][ni][1]);
                *(float2*)(Cb + (size_t)(m + 8) * N + n) = make_float2(acc[mi][ni][2], acc[mi][ni][3]);
            }
        }
    }
}

// ---------------- elementwise fp32 -> bf16 hi/lo -----------------------------
__global__ void __launch_bounds__(256) convert_pair(
    const float* __restrict__ x, bf16* __restrict__ h, bf16* __restrict__ l, size_t n)
{
    size_t i = ((size_t)blockIdx.x * 256 + threadIdx.x) * 8;
    if (i >= n) return;
    float4 a = *(const float4*)(x + i);
    float4 b = *(const float4*)(x + i + 4);
    uint32_t hw[4], lw[4];
    split2(a.x, a.y, hw[0], lw[0]);
    split2(a.z, a.w, hw[1], lw[1]);
    split2(b.x, b.y, hw[2], lw[2]);
    split2(b.z, b.w, hw[3], lw[3]);
    *(uint4*)(h + i) = make_uint4(hw[0], hw[1], hw[2], hw[3]);
    *(uint4*)(l + i) = make_uint4(lw[0], lw[1], lw[2], lw[3]);
}

// ---------------- V transpose + split: [B,N,C] -> [B,C,N] --------------------
__global__ void __launch_bounds__(256) transpose_convert(
    const float* __restrict__ v, bf16* __restrict__ th, bf16* __restrict__ tl)
{
    __shared__ float t[32][33];
    const float* vb = v + (size_t)blockIdx.z * SEQ * CDIM;
    const int c0 = blockIdx.x * 32, n0 = blockIdx.y * 32;
    for (int r = threadIdx.y; r < 32; r += 8)
        t[r][threadIdx.x] = vb[(size_t)(n0 + r) * CDIM + c0 + threadIdx.x];
    __syncthreads();
    bf16* thb = th + (size_t)blockIdx.z * CDIM * SEQ;
    bf16* tlb = tl + (size_t)blockIdx.z * CDIM * SEQ;
    for (int r = threadIdx.y; r < 32; r += 8) {
        float x = t[threadIdx.x][r];
        bf16 h = __float2bfloat16(x);
        bf16 lo = __float2bfloat16(x - __bfloat162float(h));
        size_t o = (size_t)(c0 + r) * SEQ + n0 + threadIdx.x;
        thb[o] = h; tlb[o] = lo;
    }
}

// ---------------- softmax: S fp32 -> P bf16 hi/lo ----------------------------
__global__ void __launch_bounds__(256) softmax_kernel(
    const float* __restrict__ S, bf16* __restrict__ Ph, bf16* __restrict__ Pl, float scale)
{
    const float* row = S + (size_t)blockIdx.x * SEQ;
    bf16* ph = Ph + (size_t)blockIdx.x * SEQ;
    bf16* pl = Pl + (size_t)blockIdx.x * SEQ;
    const int tid = threadIdx.x;

    float vals[8];
    float mx = -1e30f;
#pragma unroll
    for (int i = 0; i < 8; i++) {
        vals[i] = row[tid + i * 256] * scale;
        mx = fmaxf(mx, vals[i]);
    }
    __shared__ float red[256];
    red[tid] = mx; __syncthreads();
    for (int s = 128; s > 0; s >>= 1) {
        if (tid < s) red[tid] = fmaxf(red[tid], red[tid + s]);
        __syncthreads();
    }
    mx = red[0]; __syncthreads();
    float sum = 0.0f;
#pragma unroll
    for (int i = 0; i < 8; i++) { vals[i] = __expf(vals[i] - mx); sum += vals[i]; }
    red[tid] = sum; __syncthreads();
    for (int s = 128; s > 0; s >>= 1) {
        if (tid < s) red[tid] += red[tid + s];
        __syncthreads();
    }
    const float inv = 1.0f / red[0];
#pragma unroll
    for (int i = 0; i < 8; i++) {
        float p = vals[i] * inv;
        bf16 h = __float2bfloat16(p);
        bf16 lo = __float2bfloat16(p - __bfloat162float(h));
        ph[tid + i * 256] = h;
        pl[tid + i * 256] = lo;
    }
}

// ---------------- launch -----------------------------------------------------
extern "C" void kernel_launch(void* const* d_in, const int* in_sizes, int n_in,
                              void* d_out, int out_size)
{
    const float* q_x = (const float*)d_in[0];
    const float* k_x = (const float*)d_in[1];
    const float* v_x = (const float*)d_in[2];
    const float* Wq  = (const float*)d_in[3];
    const float* Wk  = (const float*)d_in[4];
    float* out = (float*)d_out;

    bf16 *qxh, *qxl, *kxh, *kxl, *wh, *wl, *qh, *ql, *kh, *kl, *vth, *vtl, *pph, *ppl;
    float* s;
    cudaGetSymbolAddress((void**)&qxh, g_qx_hi); cudaGetSymbolAddress((void**)&qxl, g_qx_lo);
    cudaGetSymbolAddress((void**)&kxh, g_kx_hi); cudaGetSymbolAddress((void**)&kxl, g_kx_lo);
    cudaGetSymbolAddress((void**)&wh,  g_w_hi);  cudaGetSymbolAddress((void**)&wl,  g_w_lo);
    cudaGetSymbolAddress((void**)&qh,  g_q_hi);  cudaGetSymbolAddress((void**)&ql,  g_q_lo);
    cudaGetSymbolAddress((void**)&kh,  g_k_hi);  cudaGetSymbolAddress((void**)&kl,  g_k_lo);
    cudaGetSymbolAddress((void**)&vth, g_vt_hi); cudaGetSymbolAddress((void**)&vtl, g_vt_lo);
    cudaGetSymbolAddress((void**)&s,   g_s);
    cudaGetSymbolAddress((void**)&pph, g_p_hi);  cudaGetSymbolAddress((void**)&ppl, g_p_lo);

    cudaFuncSetAttribute(gemm_mma<true>,  cudaFuncAttributeMaxDynamicSharedMemorySize, GSMEM_BYTES);
    cudaFuncSetAttribute(gemm_mma<false>, cudaFuncAttributeMaxDynamicSharedMemorySize, GSMEM_BYTES);

    const size_t nx = (size_t)MQ * CDIM;
    const size_t nw = (size_t)KD * CDIM;

    // 1) splits
    convert_pair<<<(unsigned)(nx / 8 / 256), 256>>>(q_x, qxh, qxl, nx);
    convert_pair<<<(unsigned)(nx / 8 / 256), 256>>>(k_x, kxh, kxl, nx);
    convert_pair<<<(unsigned)(nw / 8 / 256), 256>>>(Wq, wh, wl, nw);
    convert_pair<<<(unsigned)(nw / 8 / 256), 256>>>(Wk, wh + nw, wl + nw, nw);
    transpose_convert<<<dim3(CDIM / 32, SEQ / 32, BATCH), dim3(32, 8)>>>(v_x, vth, vtl);

    // 2) projections: Q = qx @ Wq^T, K = kx @ Wk^T (bf16 pair out)
    gemm_mma<true><<<dim3(KD / BN, MQ / BM, 1), 256, GSMEM_BYTES>>>(
        qxh, qxl, wh, wl, nullptr, qh, ql, CDIM, KD, 0, 0, 0);
    gemm_mma<true><<<dim3(KD / BN, MQ / BM, 1), 256, GSMEM_BYTES>>>(
        kxh, kxl, wh + nw, wl + nw, nullptr, kh, kl, CDIM, KD, 0, 0, 0);

    // 3) S = Q @ K^T per batch (fp32 out)
    gemm_mma<false><<<dim3(SEQ / BN, SEQ / BM, BATCH), 256, GSMEM_BYTES>>>(
        qh, ql, kh, kl, s, nullptr, nullptr, KD, SEQ,
        (long long)SEQ * KD, (long long)SEQ * KD, (long long)SEQ * SEQ);

    // 4) P = softmax(S / 768) -> bf16 pair
    softmax_kernel<<<MQ, 256>>>(s, pph, ppl, 1.0f / (float)KD);

    // 5) out = P @ Vt^T per batch (fp32 out)
    gemm_mma<false><<<dim3(CDIM / BN, SEQ / BM, BATCH), 256, GSMEM_BYTES>>>(
        pph, ppl, vth, vtl, out, nullptr, nullptr, SEQ, CDIM,
        (long long)SEQ * SEQ, (long long)CDIM * SEQ, (long long)SEQ * CDIM);
}

// round 7
// speedup vs baseline: 5.6074x; 2.2480x over previous
#include <cuda_runtime.h>
#include <cuda_bf16.h>
#include <cstdint>

#define BATCH 8
#define SEQ   2048
#define CDIM  768
#define KD    768
#define MQ    (BATCH*SEQ)

typedef __nv_bfloat16 bf16;

// ---------------- scratch (device globals; allocation-free rule) -------------
__device__ bf16  g_qx[(size_t)MQ*CDIM];
__device__ bf16  g_kx[(size_t)MQ*CDIM];
__device__ bf16  g_w [(size_t)2*KD*CDIM];
__device__ bf16  g_q [(size_t)MQ*KD];
__device__ bf16  g_k [(size_t)MQ*KD];
__device__ bf16  g_vt[(size_t)BATCH*CDIM*SEQ];
__device__ float g_s [(size_t)BATCH*SEQ*SEQ];
__device__ bf16  g_dp[(size_t)BATCH*SEQ*SEQ];
__device__ float g_bias[(size_t)BATCH*CDIM];

// ---------------- helpers ----------------------------------------------------
__device__ __forceinline__ uint32_t smem_u32(const void* p) {
    uint32_t a;
    asm("{ .reg .u64 t; cvta.to.shared.u64 t, %1; cvt.u32.u64 %0, t; }" : "=r"(a) : "l"(p));
    return a;
}
__device__ __forceinline__ void cp16(uint32_t dst, const void* src) {
    asm volatile("cp.async.cg.shared.global [%0], [%1], 16;" :: "r"(dst), "l"(src));
}
__device__ __forceinline__ void cp_commit() {
    asm volatile("cp.async.commit_group;" ::: "memory");
}
template <int N>
__device__ __forceinline__ void cp_wait() {
    asm volatile("cp.async.wait_group %0;" :: "n"(N) : "memory");
}
__device__ __forceinline__ void ldsm4(uint32_t* r, uint32_t addr) {
    asm volatile("ldmatrix.sync.aligned.m8n8.x4.shared.b16 {%0,%1,%2,%3}, [%4];"
                 : "=r"(r[0]), "=r"(r[1]), "=r"(r[2]), "=r"(r[3]) : "r"(addr));
}
__device__ __forceinline__ void mma16816(float* c, const uint32_t* a, const uint32_t* b) {
    asm volatile(
        "mma.sync.aligned.m16n8k16.row.col.f32.bf16.bf16.f32 "
        "{%0,%1,%2,%3}, {%4,%5,%6,%7}, {%8,%9}, {%0,%1,%2,%3};"
        : "+f"(c[0]), "+f"(c[1]), "+f"(c[2]), "+f"(c[3])
        : "r"(a[0]), "r"(a[1]), "r"(a[2]), "r"(a[3]), "r"(b[0]), "r"(b[1]));
}

// ---------------- single-bf16 NT GEMM via mma.sync ---------------------------
// C[m,n] = sum_k A[m,k]*B[n,k]; A,B bf16, K-major, fp32 accum.
// Block 128x128, K-chunk 32, 4-stage cp.async pipeline, 8 warps (64x32 each).
// MODE 0: C -> bf16.  MODE 1: C -> fp32.  MODE 2: C -> fp32 + bias[n].
#define BM 128
#define BN 128
#define BK 32
#define STAGES 4
#define PITCH_B 80               // bytes per smem row (32 bf16 + 8 pad)
#define MAT_B  (128*PITCH_B)     // 10240 bytes per matrix tile
#define STAGE_B (2*MAT_B)        // A, B
#define GSMEM_BYTES (STAGES*STAGE_B)

template <int MODE>
__global__ void __launch_bounds__(256) gemm_mma(
    const bf16* __restrict__ A, const bf16* __restrict__ B,
    float* __restrict__ Cf, bf16* __restrict__ Cb16,
    const float* __restrict__ bias,
    int K, int N, long long sA, long long sB, long long sC)
{
    extern __shared__ char smem[];
    const uint32_t smem0 = smem_u32(smem);

    const int tid = threadIdx.x;
    const int wid = tid >> 5;
    const int lane = tid & 31;
    const int m0 = blockIdx.y * BM;
    const int n0 = blockIdx.x * BN;
    const int warp_m = (wid & 1) * 64;
    const int warp_n = (wid >> 1) * 32;

    const bf16* pA = A + (size_t)blockIdx.z * sA;
    const bf16* pB = B + (size_t)blockIdx.z * sB;

    float acc[4][4][4];
#pragma unroll
    for (int a = 0; a < 4; a++)
#pragma unroll
        for (int b = 0; b < 4; b++)
#pragma unroll
            for (int c = 0; c < 4; c++) acc[a][b][c] = 0.0f;

    const int nch = K / BK;

    // -------- stage loader: 128 rows x 64B per matrix, 2 matrices -----------
    auto load_stage = [&](int buf, int k0) {
        const uint32_t sb = smem0 + (uint32_t)buf * STAGE_B;
#pragma unroll
        for (int p = 0; p < 2; p++) {
            const int task = tid + p * 256;
            const int row = task >> 2;
            const int seg = task & 3;
            const uint32_t off = (uint32_t)(row * PITCH_B + seg * 16);
            const int ge = k0 + seg * 8;
            cp16(sb +         off, pA + (size_t)(m0 + row) * K + ge);
            cp16(sb + MAT_B + off, pB + (size_t)(n0 + row) * K + ge);
        }
    };

#pragma unroll
    for (int s = 0; s < STAGES - 1; s++) {
        if (s < nch) load_stage(s, s * BK);
        cp_commit();
    }

    const uint32_t a_off = (uint32_t)((lane & 15) * PITCH_B + ((lane >> 4) << 3) * 2);
    const uint32_t b_off = (uint32_t)(((((lane >> 4) << 3) + (lane & 7)) * PITCH_B)
                                      + (((lane >> 3) & 1) << 3) * 2);

    for (int ch = 0; ch < nch; ch++) {
        cp_wait<STAGES - 2>();
        __syncthreads();

        const int nxt = ch + STAGES - 1;
        if (nxt < nch) load_stage(nxt % STAGES, nxt * BK);
        cp_commit();

        const uint32_t sb = smem0 + (uint32_t)(ch % STAGES) * STAGE_B;
        const uint32_t sA_ = sb, sB_ = sb + MAT_B;

#pragma unroll
        for (int ks = 0; ks < 2; ks++) {
            const uint32_t kb = (uint32_t)(ks * 16 * 2);
            uint32_t ar[4][4];
#pragma unroll
            for (int mi = 0; mi < 4; mi++)
                ldsm4(ar[mi], sA_ + (uint32_t)((warp_m + mi * 16) * PITCH_B) + a_off + kb);
            uint32_t br[2][4];
#pragma unroll
            for (int nj = 0; nj < 2; nj++)
                ldsm4(br[nj], sB_ + (uint32_t)((warp_n + nj * 16) * PITCH_B) + b_off + kb);
#pragma unroll
            for (int mi = 0; mi < 4; mi++)
#pragma unroll
                for (int ni = 0; ni < 4; ni++)
                    mma16816(acc[mi][ni], ar[mi], &br[ni >> 1][(ni & 1) * 2]);
        }
    }
    cp_wait<0>();

    // -------- epilogue ------------------------------------------------------
#pragma unroll
    for (int mi = 0; mi < 4; mi++) {
#pragma unroll
        for (int ni = 0; ni < 4; ni++) {
            const int m = m0 + warp_m + mi * 16 + (lane >> 2);
            const int n = n0 + warp_n + ni * 8 + (lane & 3) * 2;
            float c0 = acc[mi][ni][0], c1 = acc[mi][ni][1];
            float c2 = acc[mi][ni][2], c3 = acc[mi][ni][3];
            if (MODE == 0) {
                __nv_bfloat162 h0 = __floats2bfloat162_rn(c0, c1);
                __nv_bfloat162 h1 = __floats2bfloat162_rn(c2, c3);
                *(uint32_t*)(Cb16 + (size_t)m * N + n)       = reinterpret_cast<uint32_t&>(h0);
                *(uint32_t*)(Cb16 + (size_t)(m + 8) * N + n) = reinterpret_cast<uint32_t&>(h1);
            } else {
                float* Cb = Cf + (size_t)blockIdx.z * sC;
                if (MODE == 2) {
                    float2 bv = *(const float2*)(bias + (size_t)blockIdx.z * CDIM + n);
                    c0 += bv.x; c1 += bv.y; c2 += bv.x; c3 += bv.y;
                }
                *(float2*)(Cb + (size_t)m * N + n)       = make_float2(c0, c1);
                *(float2*)(Cb + (size_t)(m + 8) * N + n) = make_float2(c2, c3);
            }
        }
    }
}

// ---------------- elementwise fp32 -> bf16 -----------------------------------
__global__ void __launch_bounds__(256) convert_hi(
    const float* __restrict__ x, bf16* __restrict__ h, size_t n)
{
    size_t i = ((size_t)blockIdx.x * 256 + threadIdx.x) * 8;
    if (i >= n) return;
    float4 a = *(const float4*)(x + i);
    float4 b = *(const float4*)(x + i + 4);
    __nv_bfloat162 h0 = __floats2bfloat162_rn(a.x, a.y);
    __nv_bfloat162 h1 = __floats2bfloat162_rn(a.z, a.w);
    __nv_bfloat162 h2 = __floats2bfloat162_rn(b.x, b.y);
    __nv_bfloat162 h3 = __floats2bfloat162_rn(b.z, b.w);
    *(uint4*)(h + i) = make_uint4(
        reinterpret_cast<uint32_t&>(h0), reinterpret_cast<uint32_t&>(h1),
        reinterpret_cast<uint32_t&>(h2), reinterpret_cast<uint32_t&>(h3));
}

// ---------------- V transpose: [B,N,C] -> [B,C,N] bf16 -----------------------
__global__ void __launch_bounds__(256) transpose_convert(
    const float* __restrict__ v, bf16* __restrict__ th)
{
    __shared__ float t[32][33];
    const float* vb = v + (size_t)blockIdx.z * SEQ * CDIM;
    const int c0 = blockIdx.x * 32, n0 = blockIdx.y * 32;
    for (int r = threadIdx.y; r < 32; r += 8)
        t[r][threadIdx.x] = vb[(size_t)(n0 + r) * CDIM + c0 + threadIdx.x];
    __syncthreads();
    bf16* thb = th + (size_t)blockIdx.z * CDIM * SEQ;
    for (int r = threadIdx.y; r < 32; r += 8) {
        size_t o = (size_t)(c0 + r) * SEQ + n0 + threadIdx.x;
        thb[o] = __float2bfloat16(t[threadIdx.x][r]);
    }
}

// ---------------- column mean of V: bias[b][c] = mean_n v[b][n][c] ----------
__global__ void __launch_bounds__(256) colmean_v(
    const float* __restrict__ v, float* __restrict__ bias)
{
    const int b = blockIdx.y;
    const int c = blockIdx.x * 256 + threadIdx.x;
    const float* vb = v + (size_t)b * SEQ * CDIM + c;
    float s0 = 0.f, s1 = 0.f, s2 = 0.f, s3 = 0.f;
#pragma unroll 4
    for (int i = 0; i < SEQ; i += 4) {
        s0 += vb[(size_t)(i + 0) * CDIM];
        s1 += vb[(size_t)(i + 1) * CDIM];
        s2 += vb[(size_t)(i + 2) * CDIM];
        s3 += vb[(size_t)(i + 3) * CDIM];
    }
    bias[(size_t)b * CDIM + c] = (s0 + s1 + s2 + s3) * (1.0f / SEQ);
}

// ---------------- softmax: S fp32 -> dP = softmax - 1/SEQ (bf16) ------------
__global__ void __launch_bounds__(256) softmax_kernel(
    const float* __restrict__ S, bf16* __restrict__ Dp, float scale)
{
    const float* row = S + (size_t)blockIdx.x * SEQ;
    bf16* dp = Dp + (size_t)blockIdx.x * SEQ;
    const int tid = threadIdx.x;

    float vals[8];
    float mx = -1e30f;
#pragma unroll
    for (int i = 0; i < 8; i++) {
        vals[i] = row[tid + i * 256] * scale;
        mx = fmaxf(mx, vals[i]);
    }
    __shared__ float red[256];
    red[tid] = mx; __syncthreads();
    for (int s = 128; s > 0; s >>= 1) {
        if (tid < s) red[tid] = fmaxf(red[tid], red[tid + s]);
        __syncthreads();
    }
    mx = red[0]; __syncthreads();
    float sum = 0.0f;
#pragma unroll
    for (int i = 0; i < 8; i++) { vals[i] = __expf(vals[i] - mx); sum += vals[i]; }
    red[tid] = sum; __syncthreads();
    for (int s = 128; s > 0; s >>= 1) {
        if (tid < s) red[tid] += red[tid + s];
        __syncthreads();
    }
    const float inv = 1.0f / red[0];
    const float u = 1.0f / (float)SEQ;
#pragma unroll
    for (int i = 0; i < 8; i++)
        dp[tid + i * 256] = __float2bfloat16(vals[i] * inv - u);
}

// ---------------- launch -----------------------------------------------------
extern "C" void kernel_launch(void* const* d_in, const int* in_sizes, int n_in,
                              void* d_out, int out_size)
{
    const float* q_x = (const float*)d_in[0];
    const float* k_x = (const float*)d_in[1];
    const float* v_x = (const float*)d_in[2];
    const float* Wq  = (const float*)d_in[3];
    const float* Wk  = (const float*)d_in[4];
    float* out = (float*)d_out;

    bf16 *qx, *kx, *w, *q, *k, *vt, *dp;
    float *s, *bias;
    cudaGetSymbolAddress((void**)&qx, g_qx);
    cudaGetSymbolAddress((void**)&kx, g_kx);
    cudaGetSymbolAddress((void**)&w,  g_w);
    cudaGetSymbolAddress((void**)&q,  g_q);
    cudaGetSymbolAddress((void**)&k,  g_k);
    cudaGetSymbolAddress((void**)&vt, g_vt);
    cudaGetSymbolAddress((void**)&s,  g_s);
    cudaGetSymbolAddress((void**)&dp, g_dp);
    cudaGetSymbolAddress((void**)&bias, g_bias);

    cudaFuncSetAttribute(gemm_mma<0>, cudaFuncAttributeMaxDynamicSharedMemorySize, GSMEM_BYTES);
    cudaFuncSetAttribute(gemm_mma<1>, cudaFuncAttributeMaxDynamicSharedMemorySize, GSMEM_BYTES);
    cudaFuncSetAttribute(gemm_mma<2>, cudaFuncAttributeMaxDynamicSharedMemorySize, GSMEM_BYTES);

    const size_t nx = (size_t)MQ * CDIM;
    const size_t nw = (size_t)KD * CDIM;

    // 1) converts + V transpose + V column mean
    convert_hi<<<(unsigned)(nx / 8 / 256), 256>>>(q_x, qx, nx);
    convert_hi<<<(unsigned)(nx / 8 / 256), 256>>>(k_x, kx, nx);
    convert_hi<<<(unsigned)(nw / 8 / 256), 256>>>(Wq, w, nw);
    convert_hi<<<(unsigned)(nw / 8 / 256), 256>>>(Wk, w + nw, nw);
    transpose_convert<<<dim3(CDIM / 32, SEQ / 32, BATCH), dim3(32, 8)>>>(v_x, vt);
    colmean_v<<<dim3(CDIM / 256, BATCH), 256>>>(v_x, bias);

    // 2) projections: Q = qx @ Wq^T, K = kx @ Wk^T (bf16 out)
    gemm_mma<0><<<dim3(KD / BN, MQ / BM, 1), 256, GSMEM_BYTES>>>(
        qx, w, nullptr, q, nullptr, CDIM, KD, 0, 0, 0);
    gemm_mma<0><<<dim3(KD / BN, MQ / BM, 1), 256, GSMEM_BYTES>>>(
        kx, w + nw, nullptr, k, nullptr, CDIM, KD, 0, 0, 0);

    // 3) S = Q @ K^T per batch (fp32)
    gemm_mma<1><<<dim3(SEQ / BN, SEQ / BM, BATCH), 256, GSMEM_BYTES>>>(
        q, k, s, nullptr, nullptr, KD, SEQ,
        (long long)SEQ * KD, (long long)SEQ * KD, (long long)SEQ * SEQ);

    // 4) dP = softmax(S/768) - 1/SEQ  (bf16)
    softmax_kernel<<<MQ, 256>>>(s, dp, 1.0f / (float)KD);

    // 5) out = dP @ Vt^T + colmean(V)  per batch (fp32)
    gemm_mma<2><<<dim3(CDIM / BN, SEQ / BM, BATCH), 256, GSMEM_BYTES>>>(
        dp, vt, out, nullptr, bias, SEQ, CDIM,
        (long long)SEQ * SEQ, (long long)CDIM * SEQ, (long long)SEQ * CDIM);
}